// round 16
// baseline (speedup 1.0000x reference)
#include <cuda_runtime.h>
#include <math.h>

#define NL 128   // L lobes
#define NS 8     // samples per lobe
#define NH 16    // hidden units

typedef unsigned long long u64;

// Pre-duplicated packed table, 32B per (j,l), lane-major in l:
//   gTd[4*(j*NL+l)+0] = {A,A}   A  = sp*(U.M_j)
//   gTd[4*(j*NL+l)+1] = {B,B}   B  = sp*(V.M_j)
//   gTd[4*(j*NL+l)+2] = {C0,C0} C0 = -cp*(l.M_j)
//   gTd[4*(j*NL+l)+3] = {w2,w2}
// Loaded with one 256-bit ld.global (sm_100a) -> fully coalesced single stream.
__device__ __align__(32) u64 gTd[4 * NH * NL];
__device__ float4 gNrm[3 * NL];   // {sp*U_d, sp*V_d, cp*l_d, 0} per dim d
__device__ float  gCoef[NL];      // w / (8w + 1e-6), w = exp(sharp*(cp*|l|^2-1))

// ---- packed f32x2 helpers (PTX-only on Blackwell) ----
__device__ __forceinline__ u64 pack2(float lo, float hi) {
    u64 r; asm("mov.b64 %0, {%1, %2};" : "=l"(r) : "f"(lo), "f"(hi)); return r;
}
__device__ __forceinline__ void unpack2(u64 v, float& lo, float& hi) {
    asm("mov.b64 {%0, %1}, %2;" : "=f"(lo), "=f"(hi) : "l"(v));
}
__device__ __forceinline__ u64 fma2(u64 a, u64 b, u64 c) {
    u64 d; asm("fma.rn.f32x2 %0, %1, %2, %3;" : "=l"(d) : "l"(a), "l"(b), "l"(c)); return d;
}
__device__ __forceinline__ u64 mul2(u64 a, u64 b) {
    u64 d; asm("mul.rn.f32x2 %0, %1, %2;" : "=l"(d) : "l"(a), "l"(b)); return d;
}
__device__ __forceinline__ u64 add2(u64 a, u64 b) {
    u64 d; asm("add.rn.f32x2 %0, %1, %2;" : "=l"(d) : "l"(a), "l"(b)); return d;
}
__device__ __forceinline__ u64 dup2(float c) { return pack2(c, c); }

// 256-bit load (sm_100a): one LDG.E.256 of four u64 pairs
__device__ __forceinline__ void ldg256(const u64* p, u64& a, u64& b, u64& c, u64& d) {
    asm("ld.global.nc.v4.u64 {%0, %1, %2, %3}, [%4];"
        : "=l"(a), "=l"(b), "=l"(c), "=l"(d) : "l"(p));
}

__global__ void setup_kernel(const float* __restrict__ root_rot,
                             const float* __restrict__ lobes,
                             const float* __restrict__ lambdas,
                             const float* __restrict__ W1,
                             const float* __restrict__ W2)
{
    __shared__ float sM[3 * NH];   // M = R @ W1[3:6]  (M[d][j])
    int t = threadIdx.x;
    if (t < 3 * NH) {
        int d = t >> 4, j = t & 15;
        sM[t] = root_rot[d * 3 + 0] * W1[(3 + 0) * NH + j]
              + root_rot[d * 3 + 1] * W1[(3 + 1) * NH + j]
              + root_rot[d * 3 + 2] * W1[(3 + 2) * NH + j];
    }
    __syncthreads();

    int l = t;  // 128 threads, one per lobe
    float lx = lobes[3 * l + 0], ly = lobes[3 * l + 1], lz = lobes[3 * l + 2];
    float inv = 1.0f / (sqrtf(lx * lx + ly * ly + lz * lz) + 1e-6f);
    lx *= inv; ly *= inv; lz *= inv;

    // U = normalize(cross(z, l)) = normalize((-ly, lx, 0))
    float ux = -ly, uy = lx, uz = 0.0f;
    float un = 1.0f / (sqrtf(ux * ux + uy * uy) + 1e-6f);
    ux *= un; uy *= un;

    // V = normalize(cross(l, U))
    float vx = ly * uz - lz * uy;
    float vy = lz * ux - lx * uz;
    float vz = lx * uy - ly * ux;
    float vn = 1.0f / (sqrtf(vx * vx + vy * vy + vz * vz) + 1e-6f);
    vx *= vn; vy *= vn; vz *= vn;

    float sharp = lambdas[l];
    float rphi = acosf(1.0f - 1.0f / sharp);
    rphi = fminf(rphi, 1.0471975511965976f);  // pi/3
    float sp = sinf(rphi), cp = cosf(rphi);

    #pragma unroll
    for (int j = 0; j < NH; j++) {
        float mx = sM[j], my = sM[NH + j], mz = sM[2 * NH + j];
        float A  = sp * (ux * mx + uy * my + uz * mz);
        float B  = sp * (vx * mx + vy * my + vz * mz);
        float C0 = -cp * (lx * mx + ly * my + lz * mz);
        float w2 = W2[j];
        int base = 4 * (j * NL + l);
        gTd[base + 0] = pack2(A,  A);
        gTd[base + 1] = pack2(B,  B);
        gTd[base + 2] = pack2(C0, C0);
        gTd[base + 3] = pack2(w2, w2);
    }
    gNrm[0 * NL + l] = make_float4(sp * ux, sp * vx, cp * lx, 0.0f);
    gNrm[1 * NL + l] = make_float4(sp * uy, sp * vy, cp * ly, 0.0f);
    gNrm[2 * NL + l] = make_float4(sp * uz, sp * vz, cp * lz, 0.0f);

    float ll2 = lx * lx + ly * ly + lz * lz;
    float w = __expf(sharp * (cp * ll2 - 1.0f));
    gCoef[l] = w / (8.0f * w + 1e-6f);
}

__global__ __launch_bounds__(NL, 10) void main_kernel(
    const float* __restrict__ points,
    const float* __restrict__ normals,
    const float* __restrict__ rthr,
    const float* __restrict__ W1,
    const float* __restrict__ b1,
    const float* __restrict__ b2,
    float* __restrict__ out)
{
    int n = blockIdx.x;
    int l = threadIdx.x;

    __shared__ u64   spb2[NH];   // packed per-point bias {spb,spb}
    __shared__ float snrm[3];
    if (l < NH) {
        float px = points[3 * n + 0], py = points[3 * n + 1], pz = points[3 * n + 2];
        float s = fmaf(px, W1[l], fmaf(py, W1[NH + l], fmaf(pz, W1[2 * NH + l], b1[l])));
        spb2[l] = pack2(s, s);
    }
    if (l >= 32 && l < 35) snrm[l - 32] = normals[3 * n + (l - 32)];
    __syncthreads();

    // normal dots via 3 coalesced float4 loads
    float nU = 0.0f, nV = 0.0f, nC = 0.0f;
    #pragma unroll
    for (int d = 0; d < 3; d++) {
        float4 f = gNrm[d * NL + l];
        float nd = snrm[d];
        nU = fmaf(f.x, nd, nU);
        nV = fmaf(f.y, nd, nV);
        nC = fmaf(f.z, nd, nC);
    }
    float bb2 = b2[0];

    const float4* rp = (const float4*)(rthr + (((size_t)n * NL + l) * NS));
    float4 ra = rp[0], rb = rp[1];
    float rr[NS] = {ra.x, ra.y, ra.z, ra.w, rb.x, rb.y, rb.z, rb.w};

    // theta_s = (pi/4)*(r_s + s). Packed minimax poly on (pi/4)*r (2 samples/chain),
    // then exact rotation by s*pi/4 with negated outputs (nst=-sin, nct=-cos).
    const float H = 0.70710678118654752f;
    u64 nst2[4], nct2[4], acc2[4];
    unsigned mask = 0;
    u64 bb22 = dup2(bb2);
    #pragma unroll
    for (int p = 0; p < 4; p++) {
        u64 r2   = pack2(rr[2 * p], rr[2 * p + 1]);
        u64 phi2 = mul2(r2, dup2(0.7853981633974483f));
        u64 x2   = mul2(phi2, phi2);
        u64 ps   = fma2(x2, dup2(-1.9515295891e-4f), dup2(8.3321608736e-3f));
        ps       = fma2(x2, ps, dup2(-1.6666654611e-1f));
        u64 sp2  = fma2(mul2(phi2, x2), ps, phi2);
        u64 pc   = fma2(x2, dup2(2.443315711809948e-5f), dup2(-1.388731625493765e-3f));
        pc       = fma2(x2, pc, dup2(4.166664568298827e-2f));
        pc       = fma2(x2, pc, dup2(-0.5f));
        u64 cp2  = fma2(x2, pc, dup2(1.0f));

        float sp0, sp1, cp0, cp1;
        unpack2(sp2, sp0, sp1);
        unpack2(cp2, cp0, cp1);

        // even sample s=2p: rotation is sign/swap of (sp0, cp0)
        float nst0, nct0;
        if      (p == 0) { nst0 = -sp0; nct0 = -cp0; }   // s=0
        else if (p == 1) { nst0 = -cp0; nct0 =  sp0; }   // s=2
        else if (p == 2) { nst0 =  sp0; nct0 =  cp0; }   // s=4
        else             { nst0 =  cp0; nct0 = -sp0; }   // s=6
        // odd sample s=2p+1: needs H*(cp1 +/- sp1)
        float sum = cp1 + sp1, dif = cp1 - sp1;
        float nst1, nct1;
        if      (p == 0) { nst1 = -H * sum; nct1 = -H * dif; }  // s=1
        else if (p == 1) { nst1 = -H * dif; nct1 =  H * sum; }  // s=3
        else if (p == 2) { nst1 =  H * sum; nct1 =  H * dif; }  // s=5
        else             { nst1 =  H * dif; nct1 = -H * sum; }  // s=7

        // cos-mask bits (cd = cos*nU + sin*nV + nC = -nct*nU - nst*nV + nC)
        float cd0 = fmaf(-nct0, nU, fmaf(-nst0, nV, nC));
        float cd1 = fmaf(-nct1, nU, fmaf(-nst1, nV, nC));
        if (cd0 > 1e-6f) mask |= 1u << (2 * p);
        if (cd1 > 1e-6f) mask |= 1u << (2 * p + 1);

        nst2[p] = pack2(nst0, nst1);
        nct2[p] = pack2(nct0, nct1);
        acc2[p] = bb22;
    }

    // j outer: ONE 256-bit coalesced load of pre-duplicated operands per j
    // (no broadcast MOVs); packed bias add; s-pairs inner with scalar FMNMX ReLU.
    const u64* T = gTd + 4 * l;
    #pragma unroll
    for (int j = 0; j < NH; j++) {
        u64 A2, B2, C02, W2p;
        ldg256(T + j * 4 * NL, A2, B2, C02, W2p);
        u64 C2 = add2(C02, spb2[j]);
        #pragma unroll
        for (int p = 0; p < 4; p++) {
            u64 h2 = fma2(nct2[p], A2, fma2(nst2[p], B2, C2));
            float h0, h1;
            unpack2(h2, h0, h1);
            h0 = fmaxf(h0, 0.0f);
            h1 = fmaxf(h1, 0.0f);
            acc2[p] = fma2(pack2(h0, h1), W2p, acc2[p]);
        }
    }

    float vsum = 0.0f;
    #pragma unroll
    for (int p = 0; p < 4; p++) {
        float a0, a1;
        unpack2(acc2[p], a0, a1);
        float pred0 = __fdividef(1.0f, 1.0f + __expf(-a0));
        float pred1 = __fdividef(1.0f, 1.0f + __expf(-a1));
        vsum += (mask & (1u << (2 * p)))     ? pred0 : 0.0f;
        vsum += (mask & (1u << (2 * p + 1))) ? pred1 : 0.0f;
    }

    out[(size_t)n * NL + l] = vsum * gCoef[l];
}

extern "C" void kernel_launch(void* const* d_in, const int* in_sizes, int n_in,
                              void* d_out, int out_size)
{
    const float* points   = (const float*)d_in[0];
    const float* normals  = (const float*)d_in[1];
    const float* root_rot = (const float*)d_in[2];
    const float* lobes    = (const float*)d_in[3];
    const float* lambdas  = (const float*)d_in[4];
    const float* rthr     = (const float*)d_in[5];
    const float* W1       = (const float*)d_in[6];
    const float* b1       = (const float*)d_in[7];
    const float* W2       = (const float*)d_in[8];
    const float* b2       = (const float*)d_in[9];
    float* out = (float*)d_out;

    int N = in_sizes[0] / 3;

    setup_kernel<<<1, NL>>>(root_rot, lobes, lambdas, W1, W2);
    main_kernel<<<N, NL>>>(points, normals, rthr, W1, b1, b2, out);
}

// round 17
// speedup vs baseline: 1.2929x; 1.2929x over previous
#include <cuda_runtime.h>
#include <math.h>

#define NL 128   // L lobes
#define NS 8     // samples per lobe
#define NH 16    // hidden units

typedef unsigned long long u64;

// Fused per-(j,l) table: {A, B, C0, w2}, lane-major in l (16B lane stride -> coalesced LDG.128)
__device__ float4 gT  [NH * NL];
__device__ float4 gNrm[3 * NL];   // {sp*U_d, sp*V_d, cp*l_d, 0} per dim d
__device__ float  gCoef[NL];      // 0.5 * w / (8w + 1e-6)   (0.5 folded from sigmoid=0.5(1+tanh))

// ---- packed f32x2 helpers (PTX-only on Blackwell) ----
__device__ __forceinline__ u64 pack2(float lo, float hi) {
    u64 r; asm("mov.b64 %0, {%1, %2};" : "=l"(r) : "f"(lo), "f"(hi)); return r;
}
__device__ __forceinline__ void unpack2(u64 v, float& lo, float& hi) {
    asm("mov.b64 {%0, %1}, %2;" : "=f"(lo), "=f"(hi) : "l"(v));
}
__device__ __forceinline__ u64 fma2(u64 a, u64 b, u64 c) {
    u64 d; asm("fma.rn.f32x2 %0, %1, %2, %3;" : "=l"(d) : "l"(a), "l"(b), "l"(c)); return d;
}
__device__ __forceinline__ u64 mul2(u64 a, u64 b) {
    u64 d; asm("mul.rn.f32x2 %0, %1, %2;" : "=l"(d) : "l"(a), "l"(b)); return d;
}
__device__ __forceinline__ u64 dup2(float c) { return pack2(c, c); }

__device__ __forceinline__ float tanh_approx(float x) {
    float t; asm("tanh.approx.f32 %0, %1;" : "=f"(t) : "f"(x)); return t;
}

__global__ void setup_kernel(const float* __restrict__ root_rot,
                             const float* __restrict__ lobes,
                             const float* __restrict__ lambdas,
                             const float* __restrict__ W1,
                             const float* __restrict__ W2)
{
    __shared__ float sM[3 * NH];   // M = R @ W1[3:6]  (M[d][j])
    int t = threadIdx.x;
    if (t < 3 * NH) {
        int d = t >> 4, j = t & 15;
        sM[t] = root_rot[d * 3 + 0] * W1[(3 + 0) * NH + j]
              + root_rot[d * 3 + 1] * W1[(3 + 1) * NH + j]
              + root_rot[d * 3 + 2] * W1[(3 + 2) * NH + j];
    }
    __syncthreads();

    int l = t;  // 128 threads, one per lobe
    float lx = lobes[3 * l + 0], ly = lobes[3 * l + 1], lz = lobes[3 * l + 2];
    float inv = 1.0f / (sqrtf(lx * lx + ly * ly + lz * lz) + 1e-6f);
    lx *= inv; ly *= inv; lz *= inv;

    // U = normalize(cross(z, l)) = normalize((-ly, lx, 0))
    float ux = -ly, uy = lx, uz = 0.0f;
    float un = 1.0f / (sqrtf(ux * ux + uy * uy) + 1e-6f);
    ux *= un; uy *= un;

    // V = normalize(cross(l, U))
    float vx = ly * uz - lz * uy;
    float vy = lz * ux - lx * uz;
    float vz = lx * uy - ly * ux;
    float vn = 1.0f / (sqrtf(vx * vx + vy * vy + vz * vz) + 1e-6f);
    vx *= vn; vy *= vn; vz *= vn;

    float sharp = lambdas[l];
    float rphi = acosf(1.0f - 1.0f / sharp);
    rphi = fminf(rphi, 1.0471975511965976f);  // pi/3
    float sp = sinf(rphi), cp = cosf(rphi);

    #pragma unroll
    for (int j = 0; j < NH; j++) {
        float mx = sM[j], my = sM[NH + j], mz = sM[2 * NH + j];
        float A  = sp * (ux * mx + uy * my + uz * mz);
        float B  = sp * (vx * mx + vy * my + vz * mz);
        float C0 = -cp * (lx * mx + ly * my + lz * mz);
        gT[j * NL + l] = make_float4(A, B, C0, W2[j]);
    }
    gNrm[0 * NL + l] = make_float4(sp * ux, sp * vx, cp * lx, 0.0f);
    gNrm[1 * NL + l] = make_float4(sp * uy, sp * vy, cp * ly, 0.0f);
    gNrm[2 * NL + l] = make_float4(sp * uz, sp * vz, cp * lz, 0.0f);

    float ll2 = lx * lx + ly * ly + lz * lz;
    float w = __expf(sharp * (cp * ll2 - 1.0f));
    gCoef[l] = 0.5f * w / (8.0f * w + 1e-6f);   // 0.5 folded from sigmoid identity
}

__global__ __launch_bounds__(NL, 10) void main_kernel(
    const float* __restrict__ points,
    const float* __restrict__ normals,
    const float* __restrict__ rthr,
    const float* __restrict__ W1,
    const float* __restrict__ b1,
    const float* __restrict__ b2,
    float* __restrict__ out)
{
    int n = blockIdx.x;
    int l = threadIdx.x;

    __shared__ float spb[NH];   // per-point bias: p @ W1[:3] + b1
    __shared__ float snrm[3];
    if (l < NH) {
        float px = points[3 * n + 0], py = points[3 * n + 1], pz = points[3 * n + 2];
        spb[l] = fmaf(px, W1[l], fmaf(py, W1[NH + l], fmaf(pz, W1[2 * NH + l], b1[l])));
    }
    if (l >= 32 && l < 35) snrm[l - 32] = normals[3 * n + (l - 32)];
    __syncthreads();

    // normal dots via 3 coalesced float4 loads
    float nU = 0.0f, nV = 0.0f, nC = 0.0f;
    #pragma unroll
    for (int d = 0; d < 3; d++) {
        float4 f = gNrm[d * NL + l];
        float nd = snrm[d];
        nU = fmaf(f.x, nd, nU);
        nV = fmaf(f.y, nd, nV);
        nC = fmaf(f.z, nd, nC);
    }
    float bb2 = b2[0];

    const float4* rp = (const float4*)(rthr + (((size_t)n * NL + l) * NS));
    float4 ra = rp[0], rb = rp[1];
    float rr[NS] = {ra.x, ra.y, ra.z, ra.w, rb.x, rb.y, rb.z, rb.w};

    // theta_s = (pi/4)*(r_s + s). Packed minimax poly on (pi/4)*r (2 samples/chain),
    // then exact rotation by s*pi/4 with negated outputs (nst=-sin, nct=-cos).
    const float H = 0.70710678118654752f;
    u64 nst2[4], nct2[4], acc2[4];
    unsigned mask = 0;
    u64 bb22 = dup2(bb2);
    #pragma unroll
    for (int p = 0; p < 4; p++) {
        u64 r2   = pack2(rr[2 * p], rr[2 * p + 1]);
        u64 phi2 = mul2(r2, dup2(0.7853981633974483f));
        u64 x2   = mul2(phi2, phi2);
        u64 ps   = fma2(x2, dup2(-1.9515295891e-4f), dup2(8.3321608736e-3f));
        ps       = fma2(x2, ps, dup2(-1.6666654611e-1f));
        u64 sp2  = fma2(mul2(phi2, x2), ps, phi2);
        u64 pc   = fma2(x2, dup2(2.443315711809948e-5f), dup2(-1.388731625493765e-3f));
        pc       = fma2(x2, pc, dup2(4.166664568298827e-2f));
        pc       = fma2(x2, pc, dup2(-0.5f));
        u64 cp2  = fma2(x2, pc, dup2(1.0f));

        float sp0, sp1, cp0, cp1;
        unpack2(sp2, sp0, sp1);
        unpack2(cp2, cp0, cp1);

        // even sample s=2p: rotation is sign/swap of (sp0, cp0)
        float nst0, nct0;
        if      (p == 0) { nst0 = -sp0; nct0 = -cp0; }   // s=0
        else if (p == 1) { nst0 = -cp0; nct0 =  sp0; }   // s=2
        else if (p == 2) { nst0 =  sp0; nct0 =  cp0; }   // s=4
        else             { nst0 =  cp0; nct0 = -sp0; }   // s=6
        // odd sample s=2p+1: needs H*(cp1 +/- sp1)
        float sum = cp1 + sp1, dif = cp1 - sp1;
        float nst1, nct1;
        if      (p == 0) { nst1 = -H * sum; nct1 = -H * dif; }  // s=1
        else if (p == 1) { nst1 = -H * dif; nct1 =  H * sum; }  // s=3
        else if (p == 2) { nst1 =  H * sum; nct1 =  H * dif; }  // s=5
        else             { nst1 =  H * dif; nct1 = -H * sum; }  // s=7

        // cos-mask bits (cd = cos*nU + sin*nV + nC = -nct*nU - nst*nV + nC)
        float cd0 = fmaf(-nct0, nU, fmaf(-nst0, nV, nC));
        float cd1 = fmaf(-nct1, nU, fmaf(-nst1, nV, nC));
        if (cd0 > 1e-6f) mask |= 1u << (2 * p);
        if (cd1 > 1e-6f) mask |= 1u << (2 * p + 1);

        nst2[p] = pack2(nst0, nst1);
        nct2[p] = pack2(nct0, nct1);
        acc2[p] = bb22;
    }

    // j outer: 1 coalesced LDG.128/j, in-register broadcast packs; s-pairs inner
    const float4* T = gT + l;
    #pragma unroll
    for (int j = 0; j < NH; j++) {
        float4 t = T[j * NL];
        float Cj = t.z + spb[j];
        u64 A2  = pack2(t.x, t.x);
        u64 B2  = pack2(t.y, t.y);
        u64 C2  = pack2(Cj, Cj);
        u64 W2p = pack2(t.w, t.w);
        #pragma unroll
        for (int p = 0; p < 4; p++) {
            u64 h2 = fma2(nct2[p], A2, fma2(nst2[p], B2, C2));
            float h0, h1;
            unpack2(h2, h0, h1);
            h0 = fmaxf(h0, 0.0f);
            h1 = fmaxf(h1, 0.0f);
            acc2[p] = fma2(pack2(h0, h1), W2p, acc2[p]);
        }
    }

    // Epilogue: sigmoid(a) = 0.5*(1 + tanh(a/2)).
    // Masked sum of sigmoids = 0.5 * (sum_masked tanh(a/2) + popc(mask)); 0.5 baked in gCoef.
    float vsum = 0.0f;
    #pragma unroll
    for (int p = 0; p < 4; p++) {
        float a0, a1;
        unpack2(acc2[p], a0, a1);
        float t0 = tanh_approx(0.5f * a0);
        float t1 = tanh_approx(0.5f * a1);
        vsum += (mask & (1u << (2 * p)))     ? t0 : 0.0f;
        vsum += (mask & (1u << (2 * p + 1))) ? t1 : 0.0f;
    }
    vsum += (float)__popc(mask);

    out[(size_t)n * NL + l] = vsum * gCoef[l];
}

extern "C" void kernel_launch(void* const* d_in, const int* in_sizes, int n_in,
                              void* d_out, int out_size)
{
    const float* points   = (const float*)d_in[0];
    const float* normals  = (const float*)d_in[1];
    const float* root_rot = (const float*)d_in[2];
    const float* lobes    = (const float*)d_in[3];
    const float* lambdas  = (const float*)d_in[4];
    const float* rthr     = (const float*)d_in[5];
    const float* W1       = (const float*)d_in[6];
    const float* b1       = (const float*)d_in[7];
    const float* W2       = (const float*)d_in[8];
    const float* b2       = (const float*)d_in[9];
    float* out = (float*)d_out;

    int N = in_sizes[0] / 3;

    setup_kernel<<<1, NL>>>(root_rot, lobes, lambdas, W1, W2);
    main_kernel<<<N, NL>>>(points, normals, rthr, W1, b1, b2, out);
}